// round 12
// baseline (speedup 1.0000x reference)
#include <cuda_runtime.h>
#include <cuda_fp16.h>
#include <cstdint>

#define N_ROWS 65536
#define DIM    256
#define KCODES 1024
#define CAP    32
#define M_COLLECT 4e-4f
#define M_KEEP    2e-4f
#define NT     16            // code tiles of 64
#define NP2    4096          // pass2 blocks (16 rows each)

__device__ float  g_enorm[KCODES];      // true ||e||^2
__device__ float  g_enoff[KCODES];      // 1 + ||e||^2 (positive filter metric)
__device__ __half g_eh[KCODES * DIM];
__device__ float  g_rowmin[N_ROWS];     // offset-metric min
__device__ int    g_ccnt[N_ROWS];
__device__ float  g_cand_d[N_ROWS * CAP];   // offset-metric distances
__device__ int    g_cand_i[N_ROWS * CAP];
__device__ double g_partial[NP2];
__device__ int    g_done;

// ---------------- pass1 smem layout (fits 2 CTAs/SM) ----------------
// A: 128 x 264 halfs (pitch 528B) = 67584. B: ONE buffer, 64 x 264 halfs = 33792.
#define APITCH   264
#define TILE_A   (128 * APITCH * 2)     // 67584
#define TILE_B   (64 * APITCH * 2)      // 33792
#define SM_EN    (TILE_A + TILE_B)      // 101376 (4096B offset e-norms)
#define SM_MIN   (SM_EN + 4096)
#define SM_CNT   (SM_MIN + 512)
#define SMEM1    (SM_CNT + 512)         // 106496 B  -> 2 CTAs/SM

__device__ __forceinline__ uint32_t smem_u32(const void* p) {
    uint32_t a;
    asm("{ .reg .u64 t; cvta.to.shared.u64 t, %1; cvt.u32.u64 %0, t; }" : "=r"(a) : "l"(p));
    return a;
}

// --------------------------------------------------------------------------
// Prep: embedding norms + fp16 conversion (1024 rows only) + done reset.
// --------------------------------------------------------------------------
__global__ void prep_kernel(const float* __restrict__ emb) {
    int w    = blockIdx.x * 8 + (threadIdx.x >> 5);
    int lane = threadIdx.x & 31;
    if (blockIdx.x == 0 && threadIdx.x == 0) g_done = 0;
    if (w >= KCODES) return;
    const float* src = emb + (size_t)w * DIM;
    float4 v1 = *(const float4*)(src + lane * 8);
    float4 v2 = *(const float4*)(src + lane * 8 + 4);
    float s = v1.x*v1.x + v1.y*v1.y + v1.z*v1.z + v1.w*v1.w
            + v2.x*v2.x + v2.y*v2.y + v2.z*v2.z + v2.w*v2.w;
    __half2 h0 = __floats2half2_rn(v1.x, v1.y);
    __half2 h1 = __floats2half2_rn(v1.z, v1.w);
    __half2 h2 = __floats2half2_rn(v2.x, v2.y);
    __half2 h3 = __floats2half2_rn(v2.z, v2.w);
    uint4 packed = make_uint4(*(uint32_t*)&h0, *(uint32_t*)&h1, *(uint32_t*)&h2, *(uint32_t*)&h3);
    *(uint4*)(g_eh + (size_t)w * DIM + lane * 8) = packed;
    #pragma unroll
    for (int off = 16; off > 0; off >>= 1) s += __shfl_xor_sync(0xffffffffu, s, off);
    if (lane == 0) { g_enorm[w] = s; g_enoff[w] = 1.0f + s; }
}

// --------------------------------------------------------------------------
// Pass 1: fp16 mma.sync (f32 accum) filter — R11 occ-2 core, A converted
// in-prologue from fp32 z, offset metric d'' = (1+||e||^2) - 2 z.e (positive,
// zn-free). 256 threads, 8 warps (4m x 2n), warp tile 32x32.
// CTA = 128 z-rows x 1024 codes in 16 tiles of 64, single B buffer.
// --------------------------------------------------------------------------
__device__ __forceinline__ void mma16816(float* d, const uint32_t* a, uint32_t b0, uint32_t b1) {
    asm volatile(
        "mma.sync.aligned.m16n8k16.row.col.f32.f16.f16.f32 "
        "{%0,%1,%2,%3}, {%4,%5,%6,%7}, {%8,%9}, {%0,%1,%2,%3};"
        : "+f"(d[0]), "+f"(d[1]), "+f"(d[2]), "+f"(d[3])
        : "r"(a[0]), "r"(a[1]), "r"(a[2]), "r"(a[3]), "r"(b0), "r"(b1));
}
#define LDM_X4(r0,r1,r2,r3,addr) \
    asm volatile("ldmatrix.sync.aligned.m8n8.x4.shared.b16 {%0,%1,%2,%3}, [%4];" \
                 : "=r"(r0), "=r"(r1), "=r"(r2), "=r"(r3) : "r"(addr))
#define CP16(dst, src) \
    asm volatile("cp.async.cg.shared.global [%0], [%1], 16;" :: "r"(dst), "l"(src))
#define CP_COMMIT() asm volatile("cp.async.commit_group;" ::: "memory")
#define CP_WAIT0()  asm volatile("cp.async.wait_group 0;"  ::: "memory")

__global__ __launch_bounds__(256, 2)
void pass1_kernel(const float* __restrict__ z) {
    extern __shared__ char sm[];
    float* s_en  = (float*)(sm + SM_EN);
    int*   s_min = (int*)(sm + SM_MIN);
    int*   s_cnt = (int*)(sm + SM_CNT);

    const int tid  = threadIdx.x;
    const int lane = tid & 31;
    const int warp = tid >> 5;      // 0..7
    const int wm   = warp & 3;      // row block
    const int wn   = warp >> 2;     // code block (0..1)
    const int g    = lane >> 2;
    const int tg   = lane & 3;
    const int r0   = blockIdx.x * 128;

    const uint32_t sbA = smem_u32(sm);
    const uint32_t sbB = sbA + TILE_A;

    // per-lane ldmatrix base addresses (validated fragment layout)
    uint32_t aAddr[2];
    #pragma unroll
    for (int mt = 0; mt < 2; mt++) {
        int rowA = 32 * wm + 16 * mt + ((lane >> 3) & 1) * 8 + (lane & 7);
        aAddr[mt] = sbA + rowA * (APITCH * 2) + (lane >> 4) * 16;
    }
    uint32_t bOff[2];
    #pragma unroll
    for (int p = 0; p < 2; p++) {
        int rowB = 32 * wn + 16 * p + ((lane >> 4) & 1) * 8 + (lane & 7);
        bOff[p] = rowB * (APITCH * 2) + ((lane >> 3) & 1) * 16;
    }

    // prologue: issue B tile 0 cp.async first (overlaps A conversion below)
    #pragma unroll
    for (int i = 0; i < 8; i++) {
        int c = tid + i * 256, row = c >> 5, col = c & 31;
        CP16(sbB + row * (APITCH * 2) + col * 16, g_eh + (size_t)row * DIM + col * 8);
    }
    CP_COMMIT();

    // A tile: load z fp32, convert to fp16 smem in-register (zn not needed)
    {
        int row = tid >> 1;
        int seg = tid & 1;                 // half row = 128 floats
        const float* zr = z + (size_t)(r0 + row) * DIM + seg * 128;
        char* dst = sm + row * (APITCH * 2) + seg * 256;
        #pragma unroll
        for (int j = 0; j < 16; j++) {
            float4 u = *(const float4*)(zr + j * 8);
            float4 v = *(const float4*)(zr + j * 8 + 4);
            __half2 h0 = __floats2half2_rn(u.x, u.y);
            __half2 h1 = __floats2half2_rn(u.z, u.w);
            __half2 h2 = __floats2half2_rn(v.x, v.y);
            __half2 h3 = __floats2half2_rn(v.z, v.w);
            *(uint4*)(dst + j * 16) = make_uint4(*(uint32_t*)&h0, *(uint32_t*)&h1,
                                                 *(uint32_t*)&h2, *(uint32_t*)&h3);
        }
    }
    if (tid < 128) {
        s_min[tid] = 0x7F800000;
        s_cnt[tid] = 0;
    }
    #pragma unroll
    for (int i = 0; i < 4; i++) s_en[tid + i * 256] = g_enoff[tid + i * 256];

    CP_WAIT0();
    __syncthreads();

    float acc[2][4][4];
    #pragma unroll
    for (int mt = 0; mt < 2; mt++)
        #pragma unroll
        for (int nt = 0; nt < 4; nt++)
            #pragma unroll
            for (int e = 0; e < 4; e++) acc[mt][nt][e] = 0.0f;

    for (int ct = 0; ct < NT; ct++) {
        // ---- k-loop: ldmatrix + f32-accum mma ----
        #pragma unroll
        for (int ks = 0; ks < 16; ks++) {
            const uint32_t ko = ks * 32;
            uint32_t a0[4], a1[4], b0[4], b1[4];
            LDM_X4(a0[0], a0[1], a0[2], a0[3], aAddr[0] + ko);
            LDM_X4(a1[0], a1[1], a1[2], a1[3], aAddr[1] + ko);
            LDM_X4(b0[0], b0[1], b0[2], b0[3], sbB + bOff[0] + ko);
            LDM_X4(b1[0], b1[1], b1[2], b1[3], sbB + bOff[1] + ko);
            mma16816(acc[0][0], a0, b0[0], b0[1]);
            mma16816(acc[0][1], a0, b0[2], b0[3]);
            mma16816(acc[0][2], a0, b1[0], b1[1]);
            mma16816(acc[0][3], a0, b1[2], b1[3]);
            mma16816(acc[1][0], a1, b0[0], b0[1]);
            mma16816(acc[1][1], a1, b0[2], b0[3]);
            mma16816(acc[1][2], a1, b1[0], b1[1]);
            mma16816(acc[1][3], a1, b1[2], b1[3]);
        }

        // ---- min phase: offset distances + per-row running min ----
        #pragma unroll
        for (int mt = 0; mt < 2; mt++) {
            #pragma unroll
            for (int half_ = 0; half_ < 2; half_++) {
                const int r = 32 * wm + 16 * mt + g + 8 * half_;
                float rmin = 3.4e38f;
                #pragma unroll
                for (int nt = 0; nt < 4; nt++) {
                    const int c = ct * 64 + 32 * wn + 8 * nt + 2 * tg;
                    float d0 = s_en[c]     - 2.0f * acc[mt][nt][2 * half_];
                    float d1 = s_en[c + 1] - 2.0f * acc[mt][nt][2 * half_ + 1];
                    rmin = fminf(rmin, fminf(d0, d1));
                }
                atomicMin(&s_min[r], __float_as_int(rmin));
            }
        }
        __syncthreads();   // all k-loops done (B buffer dead) + all mins posted

        // ---- issue next B tile into the freed buffer (overlaps collect) ----
        if (ct + 1 < NT) {
            #pragma unroll
            for (int i = 0; i < 8; i++) {
                int c = tid + i * 256, row = c >> 5, col = c & 31;
                CP16(sbB + row * (APITCH * 2) + col * 16,
                     g_eh + (size_t)((ct + 1) * 64 + row) * DIM + col * 8);
            }
            CP_COMMIT();
        }

        // ---- collect phase vs converged threshold ----
        #pragma unroll
        for (int mt = 0; mt < 2; mt++) {
            #pragma unroll
            for (int half_ = 0; half_ < 2; half_++) {
                const int r = 32 * wm + 16 * mt + g + 8 * half_;
                const float thr = __int_as_float(s_min[r]) + M_COLLECT;
                #pragma unroll
                for (int nt = 0; nt < 4; nt++) {
                    const int c = ct * 64 + 32 * wn + 8 * nt + 2 * tg;
                    #pragma unroll
                    for (int e = 0; e < 2; e++) {
                        float dv = s_en[c + e] - 2.0f * acc[mt][nt][2 * half_ + e];
                        if (dv <= thr) {
                            int p = atomicAdd(&s_cnt[r], 1);
                            if (p < CAP) {
                                size_t gi = (size_t)(r0 + r) * CAP + p;
                                g_cand_d[gi] = dv;
                                g_cand_i[gi] = c + e;
                            }
                        }
                        acc[mt][nt][2 * half_ + e] = 0.0f;
                    }
                }
            }
        }

        CP_WAIT0();
        __syncthreads();
    }

    if (tid < 128) {
        g_rowmin[r0 + tid] = __int_as_float(s_min[tid]);
        g_ccnt[r0 + tid]   = s_cnt[tid];
    }
}

// --------------------------------------------------------------------------
// Pass 2: one warp per row — filter, rare exact fp32 rescore, gather, output,
// loss partial; last block finalizes the loss scalar. zn computed inline.
// --------------------------------------------------------------------------
__device__ __forceinline__ float warp_sum(float v) {
    #pragma unroll
    for (int off = 16; off > 0; off >>= 1) v += __shfl_xor_sync(0xffffffffu, v, off);
    return v;
}

__global__ __launch_bounds__(512)
void pass2_kernel(const float* __restrict__ z, const float* __restrict__ emb,
                  float* __restrict__ out) {
    __shared__ float s_l[16];
    __shared__ double sd[512];
    __shared__ bool amLast;
    const int tid  = threadIdx.x;
    const int lane = tid & 31;
    const int row  = blockIdx.x * 16 + (tid >> 5);
    const float* zr = z + (size_t)row * DIM;
    const float4 z1 = *(const float4*)(zr + lane * 8);
    const float4 z2 = *(const float4*)(zr + lane * 8 + 4);
    const float zn = warp_sum(z1.x*z1.x + z1.y*z1.y + z1.z*z1.z + z1.w*z1.w
                            + z2.x*z2.x + z2.y*z2.y + z2.z*z2.z + z2.w*z2.w);

    int widx;
    const int cnt = g_ccnt[row];
    if (cnt > CAP) {
        // overflow fallback: full exact fp32 scan
        float bd = 3.4e38f; int bi = 0;
        for (int c = 0; c < KCODES; c++) {
            const float* er = emb + (size_t)c * DIM;
            float4 e1 = *(const float4*)(er + lane * 8);
            float4 e2 = *(const float4*)(er + lane * 8 + 4);
            float dot = z1.x*e1.x + z1.y*e1.y + z1.z*e1.z + z1.w*e1.w
                      + z2.x*e2.x + z2.y*e2.y + z2.z*e2.z + z2.w*e2.w;
            dot = warp_sum(dot);
            float d = (zn + g_enorm[c]) - 2.0f * dot;
            if (d < bd) { bd = d; bi = c; }
        }
        widx = bi;
    } else {
        const float vmin = g_rowmin[row];
        float cd = 3.4e38f; int ci = -1;
        if (lane < cnt) {
            cd = g_cand_d[(size_t)row * CAP + lane];
            ci = g_cand_i[(size_t)row * CAP + lane];
        }
        unsigned keep = __ballot_sync(0xffffffffu, cd <= vmin + M_KEEP);
        if (__popc(keep) == 1) {
            widx = __shfl_sync(0xffffffffu, ci, __ffs(keep) - 1);
        } else {
            float bd = 3.4e38f; int bi = 0x7fffffff;
            unsigned m = keep;
            while (m) {
                int src = __ffs(m) - 1; m &= m - 1;
                int c = __shfl_sync(0xffffffffu, ci, src);
                const float* er = emb + (size_t)c * DIM;
                float4 e1 = *(const float4*)(er + lane * 8);
                float4 e2 = *(const float4*)(er + lane * 8 + 4);
                float dot = z1.x*e1.x + z1.y*e1.y + z1.z*e1.z + z1.w*e1.w
                          + z2.x*e2.x + z2.y*e2.y + z2.z*e2.z + z2.w*e2.w;
                dot = warp_sum(dot);
                float d = (zn + g_enorm[c]) - 2.0f * dot;
                if (d < bd || (d == bd && c < bi)) { bd = d; bi = c; }
            }
            widx = bi;
        }
    }

    const float* er = emb + (size_t)widx * DIM;
    float4 e1 = *(const float4*)(er + lane * 8);
    float4 e2 = *(const float4*)(er + lane * 8 + 4);
    float d0 = e1.x - z1.x, d1 = e1.y - z1.y, d2 = e1.z - z1.z, d3 = e1.w - z1.w;
    float d4 = e2.x - z2.x, d5 = e2.y - z2.y, d6 = e2.z - z2.z, d7 = e2.w - z2.w;
    float4 o1 = make_float4(z1.x + d0, z1.y + d1, z1.z + d2, z1.w + d3);
    float4 o2 = make_float4(z2.x + d4, z2.y + d5, z2.z + d6, z2.w + d7);
    *(float4*)(out + (size_t)row * DIM + lane * 8)     = o1;
    *(float4*)(out + (size_t)row * DIM + lane * 8 + 4) = o2;
    float lsum = d0*d0 + d1*d1 + d2*d2 + d3*d3 + d4*d4 + d5*d5 + d6*d6 + d7*d7;
    lsum = warp_sum(lsum);
    if (lane == 0) s_l[tid >> 5] = lsum;
    __syncthreads();
    if (tid == 0) {
        double acc = 0.0;
        #pragma unroll
        for (int i = 0; i < 16; i++) acc += (double)s_l[i];
        g_partial[blockIdx.x] = acc;
        __threadfence();
        amLast = (atomicAdd(&g_done, 1) == NP2 - 1);
    }
    __syncthreads();

    if (amLast) {
        double a = 0.0;
        #pragma unroll
        for (int i = 0; i < NP2 / 512; i++) a += g_partial[tid + i * 512];
        sd[tid] = a;
        __syncthreads();
        for (int st = 256; st > 0; st >>= 1) {
            if (tid < st) sd[tid] += sd[tid + st];
            __syncthreads();
        }
        if (tid == 0) {
            float m = (float)(sd[0] / ((double)N_ROWS * (double)DIM));
            out[(size_t)N_ROWS * DIM] = m + 0.25f * m;
        }
    }
}

extern "C" void kernel_launch(void* const* d_in, const int* in_sizes, int n_in,
                              void* d_out, int out_size) {
    const float* z   = (const float*)d_in[0];
    const float* emb = (const float*)d_in[1];
    float* out = (float*)d_out;

    static int cfg_done = 0;
    if (!cfg_done) {
        cudaFuncSetAttribute(pass1_kernel, cudaFuncAttributeMaxDynamicSharedMemorySize, SMEM1);
        cfg_done = 1;
    }

    prep_kernel<<<KCODES / 8, 256>>>(emb);
    pass1_kernel<<<N_ROWS / 128, 256, SMEM1>>>(z);
    pass2_kernel<<<NP2, 512>>>(z, emb, out);
}

// round 13
// speedup vs baseline: 1.0653x; 1.0653x over previous
#include <cuda_runtime.h>
#include <cuda_fp16.h>
#include <cstdint>

#define N_ROWS 65536
#define DIM    256
#define KCODES 1024
#define CAP    32
#define M_COLLECT 4e-4f
#define M_KEEP    2e-4f
#define NT     16            // code tiles of 64
#define NP2    4096          // pass2 blocks (16 rows each)

__device__ float  g_znorm[N_ROWS];
__device__ float  g_enorm[KCODES];
__device__ __half g_zh[N_ROWS * DIM];
__device__ __half g_eh[KCODES * DIM];
__device__ float  g_rowmin[N_ROWS];
__device__ int    g_ccnt[N_ROWS];
__device__ float  g_cand_d[N_ROWS * CAP];
__device__ int    g_cand_i[N_ROWS * CAP];
__device__ double g_partial[NP2];
__device__ int    g_done;

// ---------------- pass1 smem layout (fits 2 CTAs/SM) ----------------
// A: 128 x 264 halfs (pitch 528B) = 67584. B: ONE buffer, 64 x 264 halfs = 33792.
#define APITCH   264
#define TILE_A   (128 * APITCH * 2)     // 67584
#define TILE_B   (64 * APITCH * 2)      // 33792
#define SM_ZN    (TILE_A + TILE_B)      // 101376
#define SM_EN    (SM_ZN + 512)
#define SM_MIN   (SM_EN + 4096)
#define SM_CNT   (SM_MIN + 512)
#define SMEM1    (SM_CNT + 512)         // 107008 B  -> 2 CTAs/SM

__device__ __forceinline__ uint32_t smem_u32(const void* p) {
    uint32_t a;
    asm("{ .reg .u64 t; cvta.to.shared.u64 t, %1; cvt.u32.u64 %0, t; }" : "=r"(a) : "l"(p));
    return a;
}

// --------------------------------------------------------------------------
// Kernel 1: row norms + fp16 pre-conversion of z and embeddings.
// --------------------------------------------------------------------------
__global__ void norms_kernel(const float* __restrict__ z, const float* __restrict__ emb) {
    int w    = blockIdx.x * 8 + (threadIdx.x >> 5);
    int lane = threadIdx.x & 31;
    if (blockIdx.x == 0 && threadIdx.x == 0) g_done = 0;
    if (w >= N_ROWS + KCODES) return;
    const bool isz = (w < N_ROWS);
    const float* src = isz ? (z + (size_t)w * DIM) : (emb + (size_t)(w - N_ROWS) * DIM);
    float4 v1 = *(const float4*)(src + lane * 8);
    float4 v2 = *(const float4*)(src + lane * 8 + 4);
    float s = v1.x*v1.x + v1.y*v1.y + v1.z*v1.z + v1.w*v1.w
            + v2.x*v2.x + v2.y*v2.y + v2.z*v2.z + v2.w*v2.w;

    __half2 h0 = __floats2half2_rn(v1.x, v1.y);
    __half2 h1 = __floats2half2_rn(v1.z, v1.w);
    __half2 h2 = __floats2half2_rn(v2.x, v2.y);
    __half2 h3 = __floats2half2_rn(v2.z, v2.w);
    uint4 packed = make_uint4(*(uint32_t*)&h0, *(uint32_t*)&h1, *(uint32_t*)&h2, *(uint32_t*)&h3);
    __half* dsth = isz ? (g_zh + (size_t)w * DIM) : (g_eh + (size_t)(w - N_ROWS) * DIM);
    *(uint4*)(dsth + lane * 8) = packed;

    #pragma unroll
    for (int off = 16; off > 0; off >>= 1) s += __shfl_xor_sync(0xffffffffu, s, off);
    if (lane == 0) { if (isz) g_znorm[w] = s; else g_enorm[w - N_ROWS] = s; }
}

// --------------------------------------------------------------------------
// Pass 1: fp16 mma.sync (f32 accum) filter — R11 occ-2 core + cached-min
// early-out in the collect phase. 256 threads, 8 warps (4m x 2n), warp tile
// 32x32. CTA = 128 z-rows x 1024 codes in 16 tiles of 64, single B buffer.
// --------------------------------------------------------------------------
__device__ __forceinline__ void mma16816(float* d, const uint32_t* a, uint32_t b0, uint32_t b1) {
    asm volatile(
        "mma.sync.aligned.m16n8k16.row.col.f32.f16.f16.f32 "
        "{%0,%1,%2,%3}, {%4,%5,%6,%7}, {%8,%9}, {%0,%1,%2,%3};"
        : "+f"(d[0]), "+f"(d[1]), "+f"(d[2]), "+f"(d[3])
        : "r"(a[0]), "r"(a[1]), "r"(a[2]), "r"(a[3]), "r"(b0), "r"(b1));
}
#define LDM_X4(r0,r1,r2,r3,addr) \
    asm volatile("ldmatrix.sync.aligned.m8n8.x4.shared.b16 {%0,%1,%2,%3}, [%4];" \
                 : "=r"(r0), "=r"(r1), "=r"(r2), "=r"(r3) : "r"(addr))
#define CP16(dst, src) \
    asm volatile("cp.async.cg.shared.global [%0], [%1], 16;" :: "r"(dst), "l"(src))
#define CP_COMMIT() asm volatile("cp.async.commit_group;" ::: "memory")
#define CP_WAIT0()  asm volatile("cp.async.wait_group 0;"  ::: "memory")

__global__ __launch_bounds__(256, 2)
void pass1_kernel() {
    extern __shared__ char sm[];
    float* s_zn  = (float*)(sm + SM_ZN);
    float* s_en  = (float*)(sm + SM_EN);
    int*   s_min = (int*)(sm + SM_MIN);
    int*   s_cnt = (int*)(sm + SM_CNT);

    const int tid  = threadIdx.x;
    const int lane = tid & 31;
    const int warp = tid >> 5;      // 0..7
    const int wm   = warp & 3;      // row block
    const int wn   = warp >> 2;     // code block (0..1)
    const int g    = lane >> 2;
    const int tg   = lane & 3;
    const int r0   = blockIdx.x * 128;

    const uint32_t sbA = smem_u32(sm);
    const uint32_t sbB = sbA + TILE_A;

    uint32_t aAddr[2];
    #pragma unroll
    for (int mt = 0; mt < 2; mt++) {
        int rowA = 32 * wm + 16 * mt + ((lane >> 3) & 1) * 8 + (lane & 7);
        aAddr[mt] = sbA + rowA * (APITCH * 2) + (lane >> 4) * 16;
    }
    uint32_t bOff[2];
    #pragma unroll
    for (int p = 0; p < 2; p++) {
        int rowB = 32 * wn + 16 * p + ((lane >> 4) & 1) * 8 + (lane & 7);
        bOff[p] = rowB * (APITCH * 2) + ((lane >> 3) & 1) * 16;
    }

    // prologue: A tile (128 rows) + B tile 0 (64 rows), one cp.async group
    #pragma unroll
    for (int i = 0; i < 16; i++) {
        int c = tid + i * 256, row = c >> 5, col = c & 31;
        CP16(sbA + row * (APITCH * 2) + col * 16, g_zh + (size_t)(r0 + row) * DIM + col * 8);
    }
    #pragma unroll
    for (int i = 0; i < 8; i++) {
        int c = tid + i * 256, row = c >> 5, col = c & 31;
        CP16(sbB + row * (APITCH * 2) + col * 16, g_eh + (size_t)row * DIM + col * 8);
    }
    CP_COMMIT();

    if (tid < 128) {
        s_zn[tid]  = g_znorm[r0 + tid];
        s_min[tid] = 0x7F800000;
        s_cnt[tid] = 0;
    }
    #pragma unroll
    for (int i = 0; i < 4; i++) s_en[tid + i * 256] = g_enorm[tid + i * 256];

    CP_WAIT0();
    __syncthreads();

    float acc[2][4][4];
    #pragma unroll
    for (int mt = 0; mt < 2; mt++)
        #pragma unroll
        for (int nt = 0; nt < 4; nt++)
            #pragma unroll
            for (int e = 0; e < 4; e++) acc[mt][nt][e] = 0.0f;

    for (int ct = 0; ct < NT; ct++) {
        // ---- k-loop: ldmatrix + f32-accum mma ----
        #pragma unroll
        for (int ks = 0; ks < 16; ks++) {
            const uint32_t ko = ks * 32;
            uint32_t a0[4], a1[4], b0[4], b1[4];
            LDM_X4(a0[0], a0[1], a0[2], a0[3], aAddr[0] + ko);
            LDM_X4(a1[0], a1[1], a1[2], a1[3], aAddr[1] + ko);
            LDM_X4(b0[0], b0[1], b0[2], b0[3], sbB + bOff[0] + ko);
            LDM_X4(b1[0], b1[1], b1[2], b1[3], sbB + bOff[1] + ko);
            mma16816(acc[0][0], a0, b0[0], b0[1]);
            mma16816(acc[0][1], a0, b0[2], b0[3]);
            mma16816(acc[0][2], a0, b1[0], b1[1]);
            mma16816(acc[0][3], a0, b1[2], b1[3]);
            mma16816(acc[1][0], a1, b0[0], b0[1]);
            mma16816(acc[1][1], a1, b0[2], b0[3]);
            mma16816(acc[1][2], a1, b1[0], b1[1]);
            mma16816(acc[1][3], a1, b1[2], b1[3]);
        }

        // ---- min phase: distances + per-row running min (cache group mins) ----
        float rmin_c[2][2];
        #pragma unroll
        for (int mt = 0; mt < 2; mt++) {
            #pragma unroll
            for (int half_ = 0; half_ < 2; half_++) {
                const int r = 32 * wm + 16 * mt + g + 8 * half_;
                const float zn = s_zn[r];
                float rmin = 3.4e38f;
                #pragma unroll
                for (int nt = 0; nt < 4; nt++) {
                    const int c = ct * 64 + 32 * wn + 8 * nt + 2 * tg;
                    float d0 = (zn + s_en[c])     - 2.0f * acc[mt][nt][2 * half_];
                    float d1 = (zn + s_en[c + 1]) - 2.0f * acc[mt][nt][2 * half_ + 1];
                    rmin = fminf(rmin, fminf(d0, d1));
                }
                rmin_c[mt][half_] = rmin;
                atomicMin(&s_min[r], __float_as_int(rmin));
            }
        }
        __syncthreads();   // all k-loops done (B buffer dead) + all mins posted

        // ---- issue next B tile into the freed buffer (overlaps collect) ----
        if (ct + 1 < NT) {
            #pragma unroll
            for (int i = 0; i < 8; i++) {
                int c = tid + i * 256, row = c >> 5, col = c & 31;
                CP16(sbB + row * (APITCH * 2) + col * 16,
                     g_eh + (size_t)((ct + 1) * 64 + row) * DIM + col * 8);
            }
            CP_COMMIT();
        }

        // ---- collect phase: group-level early-out via cached min ----
        #pragma unroll
        for (int mt = 0; mt < 2; mt++) {
            #pragma unroll
            for (int half_ = 0; half_ < 2; half_++) {
                const int r = 32 * wm + 16 * mt + g + 8 * half_;
                const float thr = __int_as_float(s_min[r]) + M_COLLECT;
                if (rmin_c[mt][half_] <= thr) {   // rare: this group holds a candidate
                    const float zn = s_zn[r];
                    #pragma unroll
                    for (int nt = 0; nt < 4; nt++) {
                        const int c = ct * 64 + 32 * wn + 8 * nt + 2 * tg;
                        #pragma unroll
                        for (int e = 0; e < 2; e++) {
                            float dv = (zn + s_en[c + e]) - 2.0f * acc[mt][nt][2 * half_ + e];
                            if (dv <= thr) {
                                int p = atomicAdd(&s_cnt[r], 1);
                                if (p < CAP) {
                                    size_t gi = (size_t)(r0 + r) * CAP + p;
                                    g_cand_d[gi] = dv;
                                    g_cand_i[gi] = c + e;
                                }
                            }
                        }
                    }
                }
            }
        }
        // zero accumulators for the next tile
        #pragma unroll
        for (int mt = 0; mt < 2; mt++)
            #pragma unroll
            for (int nt = 0; nt < 4; nt++)
                #pragma unroll
                for (int e = 0; e < 4; e++) acc[mt][nt][e] = 0.0f;

        CP_WAIT0();
        __syncthreads();
    }

    if (tid < 128) {
        g_rowmin[r0 + tid] = __int_as_float(s_min[tid]);
        g_ccnt[r0 + tid]   = s_cnt[tid];
    }
}

// --------------------------------------------------------------------------
// Pass 2: one warp per row — filter, rare exact fp32 rescore, gather, output,
// loss partial; last block finalizes the loss scalar.
// --------------------------------------------------------------------------
__device__ __forceinline__ float warp_sum(float v) {
    #pragma unroll
    for (int off = 16; off > 0; off >>= 1) v += __shfl_xor_sync(0xffffffffu, v, off);
    return v;
}

__global__ __launch_bounds__(512)
void pass2_kernel(const float* __restrict__ z, const float* __restrict__ emb,
                  float* __restrict__ out) {
    __shared__ float s_l[16];
    __shared__ double sd[512];
    __shared__ bool amLast;
    const int tid  = threadIdx.x;
    const int lane = tid & 31;
    const int row  = blockIdx.x * 16 + (tid >> 5);
    const float* zr = z + (size_t)row * DIM;
    const float4 z1 = *(const float4*)(zr + lane * 8);
    const float4 z2 = *(const float4*)(zr + lane * 8 + 4);
    const float zn = g_znorm[row];

    int widx;
    const int cnt = g_ccnt[row];
    if (cnt > CAP) {
        float bd = 3.4e38f; int bi = 0;
        for (int c = 0; c < KCODES; c++) {
            const float* er = emb + (size_t)c * DIM;
            float4 e1 = *(const float4*)(er + lane * 8);
            float4 e2 = *(const float4*)(er + lane * 8 + 4);
            float dot = z1.x*e1.x + z1.y*e1.y + z1.z*e1.z + z1.w*e1.w
                      + z2.x*e2.x + z2.y*e2.y + z2.z*e2.z + z2.w*e2.w;
            dot = warp_sum(dot);
            float d = (zn + g_enorm[c]) - 2.0f * dot;
            if (d < bd) { bd = d; bi = c; }
        }
        widx = bi;
    } else {
        const float vmin = g_rowmin[row];
        float cd = 3.4e38f; int ci = -1;
        if (lane < cnt) {
            cd = g_cand_d[(size_t)row * CAP + lane];
            ci = g_cand_i[(size_t)row * CAP + lane];
        }
        unsigned keep = __ballot_sync(0xffffffffu, cd <= vmin + M_KEEP);
        if (__popc(keep) == 1) {
            widx = __shfl_sync(0xffffffffu, ci, __ffs(keep) - 1);
        } else {
            float bd = 3.4e38f; int bi = 0x7fffffff;
            unsigned m = keep;
            while (m) {
                int src = __ffs(m) - 1; m &= m - 1;
                int c = __shfl_sync(0xffffffffu, ci, src);
                const float* er = emb + (size_t)c * DIM;
                float4 e1 = *(const float4*)(er + lane * 8);
                float4 e2 = *(const float4*)(er + lane * 8 + 4);
                float dot = z1.x*e1.x + z1.y*e1.y + z1.z*e1.z + z1.w*e1.w
                          + z2.x*e2.x + z2.y*e2.y + z2.z*e2.z + z2.w*e2.w;
                dot = warp_sum(dot);
                float d = (zn + g_enorm[c]) - 2.0f * dot;
                if (d < bd || (d == bd && c < bi)) { bd = d; bi = c; }
            }
            widx = bi;
        }
    }

    const float* er = emb + (size_t)widx * DIM;
    float4 e1 = *(const float4*)(er + lane * 8);
    float4 e2 = *(const float4*)(er + lane * 8 + 4);
    float d0 = e1.x - z1.x, d1 = e1.y - z1.y, d2 = e1.z - z1.z, d3 = e1.w - z1.w;
    float d4 = e2.x - z2.x, d5 = e2.y - z2.y, d6 = e2.z - z2.z, d7 = e2.w - z2.w;
    float4 o1 = make_float4(z1.x + d0, z1.y + d1, z1.z + d2, z1.w + d3);
    float4 o2 = make_float4(z2.x + d4, z2.y + d5, z2.z + d6, z2.w + d7);
    *(float4*)(out + (size_t)row * DIM + lane * 8)     = o1;
    *(float4*)(out + (size_t)row * DIM + lane * 8 + 4) = o2;
    float lsum = d0*d0 + d1*d1 + d2*d2 + d3*d3 + d4*d4 + d5*d5 + d6*d6 + d7*d7;
    lsum = warp_sum(lsum);
    if (lane == 0) s_l[tid >> 5] = lsum;
    __syncthreads();
    if (tid == 0) {
        double acc = 0.0;
        #pragma unroll
        for (int i = 0; i < 16; i++) acc += (double)s_l[i];
        g_partial[blockIdx.x] = acc;
        __threadfence();
        amLast = (atomicAdd(&g_done, 1) == NP2 - 1);
    }
    __syncthreads();

    if (amLast) {
        double a = 0.0;
        #pragma unroll
        for (int i = 0; i < NP2 / 512; i++) a += g_partial[tid + i * 512];
        sd[tid] = a;
        __syncthreads();
        for (int st = 256; st > 0; st >>= 1) {
            if (tid < st) sd[tid] += sd[tid + st];
            __syncthreads();
        }
        if (tid == 0) {
            float m = (float)(sd[0] / ((double)N_ROWS * (double)DIM));
            out[(size_t)N_ROWS * DIM] = m + 0.25f * m;
        }
    }
}

extern "C" void kernel_launch(void* const* d_in, const int* in_sizes, int n_in,
                              void* d_out, int out_size) {
    const float* z   = (const float*)d_in[0];
    const float* emb = (const float*)d_in[1];
    float* out = (float*)d_out;

    static int cfg_done = 0;
    if (!cfg_done) {
        cudaFuncSetAttribute(pass1_kernel, cudaFuncAttributeMaxDynamicSharedMemorySize, SMEM1);
        cfg_done = 1;
    }

    norms_kernel<<<(N_ROWS + KCODES) / 8, 256>>>(z, emb);
    pass1_kernel<<<N_ROWS / 128, 256, SMEM1>>>();
    pass2_kernel<<<NP2, 512>>>(z, emb, out);
}

// round 14
// speedup vs baseline: 1.1805x; 1.1081x over previous
#include <cuda_runtime.h>
#include <cuda_fp16.h>
#include <cstdint>

#define N_ROWS 65536
#define DIM    256
#define KCODES 1024
#define CAP    32
#define M_COLLECT 4e-4f
#define M_KEEP    2e-4f
#define NT     16            // code tiles of 64
#define NP2    4096          // pass2 blocks (16 rows each)

__device__ float  g_znorm[N_ROWS];      // true ||z||^2 (pass2 exact rescore)
__device__ float  g_enorm[KCODES];      // true ||e||^2 (pass2 exact rescore)
__device__ float  g_enoff[KCODES];      // 1 + ||e||^2 (positive filter metric)
__device__ __half g_zh[N_ROWS * DIM];
__device__ __half g_eh[KCODES * DIM];
__device__ float  g_rowmin[N_ROWS];     // offset-metric min
__device__ int    g_ccnt[N_ROWS];
__device__ float  g_cand_d[N_ROWS * CAP];   // offset-metric distances
__device__ int    g_cand_i[N_ROWS * CAP];
__device__ double g_partial[NP2];
__device__ int    g_done;

// ---------------- pass1 smem layout (fits 2 CTAs/SM) ----------------
// A: 128 x 264 halfs (pitch 528B) = 67584. B: ONE buffer, 64 x 264 halfs = 33792.
#define APITCH   264
#define TILE_A   (128 * APITCH * 2)     // 67584
#define TILE_B   (64 * APITCH * 2)      // 33792
#define SM_EN    (TILE_A + TILE_B)      // 101376 (4096B offset e-norms)
#define SM_MIN   (SM_EN + 4096)
#define SM_CNT   (SM_MIN + 512)
#define SMEM1    (SM_CNT + 512)         // 106496 B  -> 2 CTAs/SM

__device__ __forceinline__ uint32_t smem_u32(const void* p) {
    uint32_t a;
    asm("{ .reg .u64 t; cvta.to.shared.u64 t, %1; cvt.u32.u64 %0, t; }" : "=r"(a) : "l"(p));
    return a;
}

// --------------------------------------------------------------------------
// Kernel 1: row norms + fp16 pre-conversion of z and embeddings.
// --------------------------------------------------------------------------
__global__ void norms_kernel(const float* __restrict__ z, const float* __restrict__ emb) {
    int w    = blockIdx.x * 8 + (threadIdx.x >> 5);
    int lane = threadIdx.x & 31;
    if (blockIdx.x == 0 && threadIdx.x == 0) g_done = 0;
    if (w >= N_ROWS + KCODES) return;
    const bool isz = (w < N_ROWS);
    const float* src = isz ? (z + (size_t)w * DIM) : (emb + (size_t)(w - N_ROWS) * DIM);
    float4 v1 = *(const float4*)(src + lane * 8);
    float4 v2 = *(const float4*)(src + lane * 8 + 4);
    float s = v1.x*v1.x + v1.y*v1.y + v1.z*v1.z + v1.w*v1.w
            + v2.x*v2.x + v2.y*v2.y + v2.z*v2.z + v2.w*v2.w;

    __half2 h0 = __floats2half2_rn(v1.x, v1.y);
    __half2 h1 = __floats2half2_rn(v1.z, v1.w);
    __half2 h2 = __floats2half2_rn(v2.x, v2.y);
    __half2 h3 = __floats2half2_rn(v2.z, v2.w);
    uint4 packed = make_uint4(*(uint32_t*)&h0, *(uint32_t*)&h1, *(uint32_t*)&h2, *(uint32_t*)&h3);
    __half* dsth = isz ? (g_zh + (size_t)w * DIM) : (g_eh + (size_t)(w - N_ROWS) * DIM);
    *(uint4*)(dsth + lane * 8) = packed;

    #pragma unroll
    for (int off = 16; off > 0; off >>= 1) s += __shfl_xor_sync(0xffffffffu, s, off);
    if (lane == 0) {
        if (isz) g_znorm[w] = s;
        else { g_enorm[w - N_ROWS] = s; g_enoff[w - N_ROWS] = 1.0f + s; }
    }
}

// --------------------------------------------------------------------------
// Pass 1: fp16 mma.sync (f32 accum) filter — R13 occ-2 core + zn-free offset
// metric d'' = (1+||e||^2) - 2 z.e (positive -> bits-atomicMin OK) + e-norms
// registered once per tile + cached-min early-out collect.
// 256 threads, 8 warps (4m x 2n), warp tile 32x32.
// CTA = 128 z-rows x 1024 codes in 16 tiles of 64, single B buffer.
// --------------------------------------------------------------------------
__device__ __forceinline__ void mma16816(float* d, const uint32_t* a, uint32_t b0, uint32_t b1) {
    asm volatile(
        "mma.sync.aligned.m16n8k16.row.col.f32.f16.f16.f32 "
        "{%0,%1,%2,%3}, {%4,%5,%6,%7}, {%8,%9}, {%0,%1,%2,%3};"
        : "+f"(d[0]), "+f"(d[1]), "+f"(d[2]), "+f"(d[3])
        : "r"(a[0]), "r"(a[1]), "r"(a[2]), "r"(a[3]), "r"(b0), "r"(b1));
}
#define LDM_X4(r0,r1,r2,r3,addr) \
    asm volatile("ldmatrix.sync.aligned.m8n8.x4.shared.b16 {%0,%1,%2,%3}, [%4];" \
                 : "=r"(r0), "=r"(r1), "=r"(r2), "=r"(r3) : "r"(addr))
#define CP16(dst, src) \
    asm volatile("cp.async.cg.shared.global [%0], [%1], 16;" :: "r"(dst), "l"(src))
#define CP_COMMIT() asm volatile("cp.async.commit_group;" ::: "memory")
#define CP_WAIT0()  asm volatile("cp.async.wait_group 0;"  ::: "memory")

__global__ __launch_bounds__(256, 2)
void pass1_kernel() {
    extern __shared__ char sm[];
    float* s_en  = (float*)(sm + SM_EN);
    int*   s_min = (int*)(sm + SM_MIN);
    int*   s_cnt = (int*)(sm + SM_CNT);

    const int tid  = threadIdx.x;
    const int lane = tid & 31;
    const int warp = tid >> 5;      // 0..7
    const int wm   = warp & 3;      // row block
    const int wn   = warp >> 2;     // code block (0..1)
    const int g    = lane >> 2;
    const int tg   = lane & 3;
    const int r0   = blockIdx.x * 128;

    const uint32_t sbA = smem_u32(sm);
    const uint32_t sbB = sbA + TILE_A;

    uint32_t aAddr[2];
    #pragma unroll
    for (int mt = 0; mt < 2; mt++) {
        int rowA = 32 * wm + 16 * mt + ((lane >> 3) & 1) * 8 + (lane & 7);
        aAddr[mt] = sbA + rowA * (APITCH * 2) + (lane >> 4) * 16;
    }
    uint32_t bOff[2];
    #pragma unroll
    for (int p = 0; p < 2; p++) {
        int rowB = 32 * wn + 16 * p + ((lane >> 4) & 1) * 8 + (lane & 7);
        bOff[p] = rowB * (APITCH * 2) + ((lane >> 3) & 1) * 16;
    }

    // prologue: A tile (128 rows) + B tile 0 (64 rows), one cp.async group
    #pragma unroll
    for (int i = 0; i < 16; i++) {
        int c = tid + i * 256, row = c >> 5, col = c & 31;
        CP16(sbA + row * (APITCH * 2) + col * 16, g_zh + (size_t)(r0 + row) * DIM + col * 8);
    }
    #pragma unroll
    for (int i = 0; i < 8; i++) {
        int c = tid + i * 256, row = c >> 5, col = c & 31;
        CP16(sbB + row * (APITCH * 2) + col * 16, g_eh + (size_t)row * DIM + col * 8);
    }
    CP_COMMIT();

    if (tid < 128) {
        s_min[tid] = 0x7F800000;
        s_cnt[tid] = 0;
    }
    #pragma unroll
    for (int i = 0; i < 4; i++) s_en[tid + i * 256] = g_enoff[tid + i * 256];

    CP_WAIT0();
    __syncthreads();

    float acc[2][4][4];
    #pragma unroll
    for (int mt = 0; mt < 2; mt++)
        #pragma unroll
        for (int nt = 0; nt < 4; nt++)
            #pragma unroll
            for (int e = 0; e < 4; e++) acc[mt][nt][e] = 0.0f;

    for (int ct = 0; ct < NT; ct++) {
        // ---- k-loop: ldmatrix + f32-accum mma ----
        #pragma unroll
        for (int ks = 0; ks < 16; ks++) {
            const uint32_t ko = ks * 32;
            uint32_t a0[4], a1[4], b0[4], b1[4];
            LDM_X4(a0[0], a0[1], a0[2], a0[3], aAddr[0] + ko);
            LDM_X4(a1[0], a1[1], a1[2], a1[3], aAddr[1] + ko);
            LDM_X4(b0[0], b0[1], b0[2], b0[3], sbB + bOff[0] + ko);
            LDM_X4(b1[0], b1[1], b1[2], b1[3], sbB + bOff[1] + ko);
            mma16816(acc[0][0], a0, b0[0], b0[1]);
            mma16816(acc[0][1], a0, b0[2], b0[3]);
            mma16816(acc[0][2], a0, b1[0], b1[1]);
            mma16816(acc[0][3], a0, b1[2], b1[3]);
            mma16816(acc[1][0], a1, b0[0], b0[1]);
            mma16816(acc[1][1], a1, b0[2], b0[3]);
            mma16816(acc[1][2], a1, b1[0], b1[1]);
            mma16816(acc[1][3], a1, b1[2], b1[3]);
        }

        // ---- load this thread's 8 offset e-norms once (shared by all groups) ----
        float2 enp[4];
        #pragma unroll
        for (int nt = 0; nt < 4; nt++)
            enp[nt] = *(float2*)&s_en[ct * 64 + 32 * wn + 8 * nt + 2 * tg];

        // ---- min phase: d'' = enoff - 2*acc (zn-free), per-row running min ----
        float rmin_c[2][2];
        #pragma unroll
        for (int mt = 0; mt < 2; mt++) {
            #pragma unroll
            for (int half_ = 0; half_ < 2; half_++) {
                const int r = 32 * wm + 16 * mt + g + 8 * half_;
                float rmin = 3.4e38f;
                #pragma unroll
                for (int nt = 0; nt < 4; nt++) {
                    float d0 = enp[nt].x - 2.0f * acc[mt][nt][2 * half_];
                    float d1 = enp[nt].y - 2.0f * acc[mt][nt][2 * half_ + 1];
                    rmin = fminf(rmin, fminf(d0, d1));
                }
                rmin_c[mt][half_] = rmin;
                atomicMin(&s_min[r], __float_as_int(rmin));
            }
        }
        __syncthreads();   // all k-loops done (B buffer dead) + all mins posted

        // ---- issue next B tile into the freed buffer (overlaps collect) ----
        if (ct + 1 < NT) {
            #pragma unroll
            for (int i = 0; i < 8; i++) {
                int c = tid + i * 256, row = c >> 5, col = c & 31;
                CP16(sbB + row * (APITCH * 2) + col * 16,
                     g_eh + (size_t)((ct + 1) * 64 + row) * DIM + col * 8);
            }
            CP_COMMIT();
        }

        // ---- collect phase: group-level early-out via cached min ----
        #pragma unroll
        for (int mt = 0; mt < 2; mt++) {
            #pragma unroll
            for (int half_ = 0; half_ < 2; half_++) {
                const int r = 32 * wm + 16 * mt + g + 8 * half_;
                const float thr = __int_as_float(s_min[r]) + M_COLLECT;
                if (rmin_c[mt][half_] <= thr) {   // rare: this group holds a candidate
                    #pragma unroll
                    for (int nt = 0; nt < 4; nt++) {
                        const int c = ct * 64 + 32 * wn + 8 * nt + 2 * tg;
                        #pragma unroll
                        for (int e = 0; e < 2; e++) {
                            float en = e ? enp[nt].y : enp[nt].x;
                            float dv = en - 2.0f * acc[mt][nt][2 * half_ + e];
                            if (dv <= thr) {
                                int p = atomicAdd(&s_cnt[r], 1);
                                if (p < CAP) {
                                    size_t gi = (size_t)(r0 + r) * CAP + p;
                                    g_cand_d[gi] = dv;
                                    g_cand_i[gi] = c + e;
                                }
                            }
                        }
                    }
                }
            }
        }
        // zero accumulators for the next tile
        #pragma unroll
        for (int mt = 0; mt < 2; mt++)
            #pragma unroll
            for (int nt = 0; nt < 4; nt++)
                #pragma unroll
                for (int e = 0; e < 4; e++) acc[mt][nt][e] = 0.0f;

        CP_WAIT0();
        __syncthreads();
    }

    if (tid < 128) {
        g_rowmin[r0 + tid] = __int_as_float(s_min[tid]);
        g_ccnt[r0 + tid]   = s_cnt[tid];
    }
}

// --------------------------------------------------------------------------
// Pass 2: one warp per row — filter (offset space), rare exact fp32 rescore
// (true-distance space), gather, output, loss partial; last block finalizes.
// --------------------------------------------------------------------------
__device__ __forceinline__ float warp_sum(float v) {
    #pragma unroll
    for (int off = 16; off > 0; off >>= 1) v += __shfl_xor_sync(0xffffffffu, v, off);
    return v;
}

__global__ __launch_bounds__(512)
void pass2_kernel(const float* __restrict__ z, const float* __restrict__ emb,
                  float* __restrict__ out) {
    __shared__ float s_l[16];
    __shared__ double sd[512];
    __shared__ bool amLast;
    const int tid  = threadIdx.x;
    const int lane = tid & 31;
    const int row  = blockIdx.x * 16 + (tid >> 5);
    const float* zr = z + (size_t)row * DIM;
    const float4 z1 = *(const float4*)(zr + lane * 8);
    const float4 z2 = *(const float4*)(zr + lane * 8 + 4);
    const float zn = g_znorm[row];

    int widx;
    const int cnt = g_ccnt[row];
    if (cnt > CAP) {
        float bd = 3.4e38f; int bi = 0;
        for (int c = 0; c < KCODES; c++) {
            const float* er = emb + (size_t)c * DIM;
            float4 e1 = *(const float4*)(er + lane * 8);
            float4 e2 = *(const float4*)(er + lane * 8 + 4);
            float dot = z1.x*e1.x + z1.y*e1.y + z1.z*e1.z + z1.w*e1.w
                      + z2.x*e2.x + z2.y*e2.y + z2.z*e2.z + z2.w*e2.w;
            dot = warp_sum(dot);
            float d = (zn + g_enorm[c]) - 2.0f * dot;
            if (d < bd) { bd = d; bi = c; }
        }
        widx = bi;
    } else {
        const float vmin = g_rowmin[row];
        float cd = 3.4e38f; int ci = -1;
        if (lane < cnt) {
            cd = g_cand_d[(size_t)row * CAP + lane];
            ci = g_cand_i[(size_t)row * CAP + lane];
        }
        unsigned keep = __ballot_sync(0xffffffffu, cd <= vmin + M_KEEP);
        if (__popc(keep) == 1) {
            widx = __shfl_sync(0xffffffffu, ci, __ffs(keep) - 1);
        } else {
            float bd = 3.4e38f; int bi = 0x7fffffff;
            unsigned m = keep;
            while (m) {
                int src = __ffs(m) - 1; m &= m - 1;
                int c = __shfl_sync(0xffffffffu, ci, src);
                const float* er = emb + (size_t)c * DIM;
                float4 e1 = *(const float4*)(er + lane * 8);
                float4 e2 = *(const float4*)(er + lane * 8 + 4);
                float dot = z1.x*e1.x + z1.y*e1.y + z1.z*e1.z + z1.w*e1.w
                          + z2.x*e2.x + z2.y*e2.y + z2.z*e2.z + z2.w*e2.w;
                dot = warp_sum(dot);
                float d = (zn + g_enorm[c]) - 2.0f * dot;
                if (d < bd || (d == bd && c < bi)) { bd = d; bi = c; }
            }
            widx = bi;
        }
    }

    const float* er = emb + (size_t)widx * DIM;
    float4 e1 = *(const float4*)(er + lane * 8);
    float4 e2 = *(const float4*)(er + lane * 8 + 4);
    float d0 = e1.x - z1.x, d1 = e1.y - z1.y, d2 = e1.z - z1.z, d3 = e1.w - z1.w;
    float d4 = e2.x - z2.x, d5 = e2.y - z2.y, d6 = e2.z - z2.z, d7 = e2.w - z2.w;
    float4 o1 = make_float4(z1.x + d0, z1.y + d1, z1.z + d2, z1.w + d3);
    float4 o2 = make_float4(z2.x + d4, z2.y + d5, z2.z + d6, z2.w + d7);
    *(float4*)(out + (size_t)row * DIM + lane * 8)     = o1;
    *(float4*)(out + (size_t)row * DIM + lane * 8 + 4) = o2;
    float lsum = d0*d0 + d1*d1 + d2*d2 + d3*d3 + d4*d4 + d5*d5 + d6*d6 + d7*d7;
    lsum = warp_sum(lsum);
    if (lane == 0) s_l[tid >> 5] = lsum;
    __syncthreads();
    if (tid == 0) {
        double acc = 0.0;
        #pragma unroll
        for (int i = 0; i < 16; i++) acc += (double)s_l[i];
        g_partial[blockIdx.x] = acc;
        __threadfence();
        amLast = (atomicAdd(&g_done, 1) == NP2 - 1);
    }
    __syncthreads();

    if (amLast) {
        double a = 0.0;
        #pragma unroll
        for (int i = 0; i < NP2 / 512; i++) a += g_partial[tid + i * 512];
        sd[tid] = a;
        __syncthreads();
        for (int st = 256; st > 0; st >>= 1) {
            if (tid < st) sd[tid] += sd[tid + st];
            __syncthreads();
        }
        if (tid == 0) {
            float m = (float)(sd[0] / ((double)N_ROWS * (double)DIM));
            out[(size_t)N_ROWS * DIM] = m + 0.25f * m;
        }
    }
}

extern "C" void kernel_launch(void* const* d_in, const int* in_sizes, int n_in,
                              void* d_out, int out_size) {
    const float* z   = (const float*)d_in[0];
    const float* emb = (const float*)d_in[1];
    float* out = (float*)d_out;

    static int cfg_done = 0;
    if (!cfg_done) {
        cudaFuncSetAttribute(pass1_kernel, cudaFuncAttributeMaxDynamicSharedMemorySize, SMEM1);
        cfg_done = 1;
    }

    norms_kernel<<<(N_ROWS + KCODES) / 8, 256>>>(z, emb);
    pass1_kernel<<<N_ROWS / 128, 256, SMEM1>>>();
    pass2_kernel<<<NP2, 512>>>(z, emb, out);
}

// round 15
// speedup vs baseline: 1.1955x; 1.0127x over previous
#include <cuda_runtime.h>
#include <cuda_fp16.h>
#include <cstdint>

#define N_ROWS 65536
#define DIM    256
#define KCODES 1024
#define CAP    32
#define M_COLLECT 4e-4f
#define M_KEEP    2e-4f
#define NT     16            // code tiles of 64
#define NP2    4096          // pass2 blocks (16 rows each)

__device__ float  g_enorm[KCODES];      // true ||e||^2 (pass2 exact rescore)
__device__ float  g_enoff[KCODES];      // 1 + ||e||^2 (positive filter metric)
__device__ __half g_eh[KCODES * DIM];
__device__ float  g_rowmin[N_ROWS];     // offset-metric min
__device__ int    g_ccnt[N_ROWS];
__device__ float  g_cand_d[N_ROWS * CAP];   // offset-metric distances
__device__ int    g_cand_i[N_ROWS * CAP];
__device__ double g_partial[NP2];
__device__ int    g_done;

// ---------------- pass1 smem layout (fits 2 CTAs/SM) ----------------
// A: 128 x 264 halfs (pitch 528B) = 67584. B: ONE buffer, 64 x 264 halfs = 33792.
#define APITCH   264
#define TILE_A   (128 * APITCH * 2)     // 67584
#define TILE_B   (64 * APITCH * 2)      // 33792
#define SM_EN    (TILE_A + TILE_B)      // 101376 (4096B offset e-norms)
#define SM_MIN   (SM_EN + 4096)
#define SM_CNT   (SM_MIN + 512)
#define SMEM1    (SM_CNT + 512)         // 106496 B  -> 2 CTAs/SM

__device__ __forceinline__ uint32_t smem_u32(const void* p) {
    uint32_t a;
    asm("{ .reg .u64 t; cvta.to.shared.u64 t, %1; cvt.u32.u64 %0, t; }" : "=r"(a) : "l"(p));
    return a;
}

// --------------------------------------------------------------------------
// Prep: embedding norms + fp16 conversion (1024 rows only) + done reset.
// --------------------------------------------------------------------------
__global__ void prep_kernel(const float* __restrict__ emb) {
    int w    = blockIdx.x * 8 + (threadIdx.x >> 5);
    int lane = threadIdx.x & 31;
    if (blockIdx.x == 0 && threadIdx.x == 0) g_done = 0;
    if (w >= KCODES) return;
    const float* src = emb + (size_t)w * DIM;
    float4 v1 = *(const float4*)(src + lane * 8);
    float4 v2 = *(const float4*)(src + lane * 8 + 4);
    float s = v1.x*v1.x + v1.y*v1.y + v1.z*v1.z + v1.w*v1.w
            + v2.x*v2.x + v2.y*v2.y + v2.z*v2.z + v2.w*v2.w;
    __half2 h0 = __floats2half2_rn(v1.x, v1.y);
    __half2 h1 = __floats2half2_rn(v1.z, v1.w);
    __half2 h2 = __floats2half2_rn(v2.x, v2.y);
    __half2 h3 = __floats2half2_rn(v2.z, v2.w);
    uint4 packed = make_uint4(*(uint32_t*)&h0, *(uint32_t*)&h1, *(uint32_t*)&h2, *(uint32_t*)&h3);
    *(uint4*)(g_eh + (size_t)w * DIM + lane * 8) = packed;
    #pragma unroll
    for (int off = 16; off > 0; off >>= 1) s += __shfl_xor_sync(0xffffffffu, s, off);
    if (lane == 0) { g_enorm[w] = s; g_enoff[w] = 1.0f + s; }
}

// --------------------------------------------------------------------------
// Pass 1: fp16 mma.sync (f32 accum) filter — R14 occ-2 core; A tile converted
// in-prologue from fp32 z with COALESCED loads (warp = 32 consecutive float4).
// Metric d'' = (1+||e||^2) - 2 z.e (positive -> bits-atomicMin OK), e-norms
// registered once per tile, cached-min early-out collect.
// 256 threads, 8 warps (4m x 2n), warp tile 32x32.
// CTA = 128 z-rows x 1024 codes in 16 tiles of 64, single B buffer.
// --------------------------------------------------------------------------
__device__ __forceinline__ void mma16816(float* d, const uint32_t* a, uint32_t b0, uint32_t b1) {
    asm volatile(
        "mma.sync.aligned.m16n8k16.row.col.f32.f16.f16.f32 "
        "{%0,%1,%2,%3}, {%4,%5,%6,%7}, {%8,%9}, {%0,%1,%2,%3};"
        : "+f"(d[0]), "+f"(d[1]), "+f"(d[2]), "+f"(d[3])
        : "r"(a[0]), "r"(a[1]), "r"(a[2]), "r"(a[3]), "r"(b0), "r"(b1));
}
#define LDM_X4(r0,r1,r2,r3,addr) \
    asm volatile("ldmatrix.sync.aligned.m8n8.x4.shared.b16 {%0,%1,%2,%3}, [%4];" \
                 : "=r"(r0), "=r"(r1), "=r"(r2), "=r"(r3) : "r"(addr))
#define CP16(dst, src) \
    asm volatile("cp.async.cg.shared.global [%0], [%1], 16;" :: "r"(dst), "l"(src))
#define CP_COMMIT() asm volatile("cp.async.commit_group;" ::: "memory")
#define CP_WAIT0()  asm volatile("cp.async.wait_group 0;"  ::: "memory")

__global__ __launch_bounds__(256, 2)
void pass1_kernel(const float* __restrict__ z) {
    extern __shared__ char sm[];
    float* s_en  = (float*)(sm + SM_EN);
    int*   s_min = (int*)(sm + SM_MIN);
    int*   s_cnt = (int*)(sm + SM_CNT);

    const int tid  = threadIdx.x;
    const int lane = tid & 31;
    const int warp = tid >> 5;      // 0..7
    const int wm   = warp & 3;      // row block
    const int wn   = warp >> 2;     // code block (0..1)
    const int g    = lane >> 2;
    const int tg   = lane & 3;
    const int r0   = blockIdx.x * 128;

    const uint32_t sbA = smem_u32(sm);
    const uint32_t sbB = sbA + TILE_A;

    uint32_t aAddr[2];
    #pragma unroll
    for (int mt = 0; mt < 2; mt++) {
        int rowA = 32 * wm + 16 * mt + ((lane >> 3) & 1) * 8 + (lane & 7);
        aAddr[mt] = sbA + rowA * (APITCH * 2) + (lane >> 4) * 16;
    }
    uint32_t bOff[2];
    #pragma unroll
    for (int p = 0; p < 2; p++) {
        int rowB = 32 * wn + 16 * p + ((lane >> 4) & 1) * 8 + (lane & 7);
        bOff[p] = rowB * (APITCH * 2) + ((lane >> 3) & 1) * 16;
    }

    // prologue: issue B tile 0 cp.async first (overlaps A conversion below)
    #pragma unroll
    for (int i = 0; i < 8; i++) {
        int c = tid + i * 256, row = c >> 5, col = c & 31;
        CP16(sbB + row * (APITCH * 2) + col * 16, g_eh + (size_t)row * DIM + col * 8);
    }
    CP_COMMIT();

    // A tile: coalesced fp32 z load -> fp16 convert -> STS (pitch-264 layout).
    // c = tid + i*256: warp covers 32 consecutive float4 (128B transactions).
    #pragma unroll
    for (int i = 0; i < 32; i++) {
        int c   = tid + i * 256;
        int row = c >> 6;            // 64 float4 per row
        int col = c & 63;            // float4 index within row
        float4 v = *(const float4*)(z + (size_t)(r0 + row) * DIM + col * 4);
        __half2 h0 = __floats2half2_rn(v.x, v.y);
        __half2 h1 = __floats2half2_rn(v.z, v.w);
        *(uint2*)(sm + row * (APITCH * 2) + col * 8) =
            make_uint2(*(uint32_t*)&h0, *(uint32_t*)&h1);
    }

    if (tid < 128) {
        s_min[tid] = 0x7F800000;
        s_cnt[tid] = 0;
    }
    #pragma unroll
    for (int i = 0; i < 4; i++) s_en[tid + i * 256] = g_enoff[tid + i * 256];

    CP_WAIT0();
    __syncthreads();

    float acc[2][4][4];
    #pragma unroll
    for (int mt = 0; mt < 2; mt++)
        #pragma unroll
        for (int nt = 0; nt < 4; nt++)
            #pragma unroll
            for (int e = 0; e < 4; e++) acc[mt][nt][e] = 0.0f;

    for (int ct = 0; ct < NT; ct++) {
        // ---- k-loop: ldmatrix + f32-accum mma ----
        #pragma unroll
        for (int ks = 0; ks < 16; ks++) {
            const uint32_t ko = ks * 32;
            uint32_t a0[4], a1[4], b0[4], b1[4];
            LDM_X4(a0[0], a0[1], a0[2], a0[3], aAddr[0] + ko);
            LDM_X4(a1[0], a1[1], a1[2], a1[3], aAddr[1] + ko);
            LDM_X4(b0[0], b0[1], b0[2], b0[3], sbB + bOff[0] + ko);
            LDM_X4(b1[0], b1[1], b1[2], b1[3], sbB + bOff[1] + ko);
            mma16816(acc[0][0], a0, b0[0], b0[1]);
            mma16816(acc[0][1], a0, b0[2], b0[3]);
            mma16816(acc[0][2], a0, b1[0], b1[1]);
            mma16816(acc[0][3], a0, b1[2], b1[3]);
            mma16816(acc[1][0], a1, b0[0], b0[1]);
            mma16816(acc[1][1], a1, b0[2], b0[3]);
            mma16816(acc[1][2], a1, b1[0], b1[1]);
            mma16816(acc[1][3], a1, b1[2], b1[3]);
        }

        // ---- load this thread's 8 offset e-norms once ----
        float2 enp[4];
        #pragma unroll
        for (int nt = 0; nt < 4; nt++)
            enp[nt] = *(float2*)&s_en[ct * 64 + 32 * wn + 8 * nt + 2 * tg];

        // ---- min phase: d'' = enoff - 2*acc (zn-free), per-row running min ----
        float rmin_c[2][2];
        #pragma unroll
        for (int mt = 0; mt < 2; mt++) {
            #pragma unroll
            for (int half_ = 0; half_ < 2; half_++) {
                const int r = 32 * wm + 16 * mt + g + 8 * half_;
                float rmin = 3.4e38f;
                #pragma unroll
                for (int nt = 0; nt < 4; nt++) {
                    float d0 = enp[nt].x - 2.0f * acc[mt][nt][2 * half_];
                    float d1 = enp[nt].y - 2.0f * acc[mt][nt][2 * half_ + 1];
                    rmin = fminf(rmin, fminf(d0, d1));
                }
                rmin_c[mt][half_] = rmin;
                atomicMin(&s_min[r], __float_as_int(rmin));
            }
        }
        __syncthreads();   // all k-loops done (B buffer dead) + all mins posted

        // ---- issue next B tile into the freed buffer (overlaps collect) ----
        if (ct + 1 < NT) {
            #pragma unroll
            for (int i = 0; i < 8; i++) {
                int c = tid + i * 256, row = c >> 5, col = c & 31;
                CP16(sbB + row * (APITCH * 2) + col * 16,
                     g_eh + (size_t)((ct + 1) * 64 + row) * DIM + col * 8);
            }
            CP_COMMIT();
        }

        // ---- collect phase: group-level early-out via cached min ----
        #pragma unroll
        for (int mt = 0; mt < 2; mt++) {
            #pragma unroll
            for (int half_ = 0; half_ < 2; half_++) {
                const int r = 32 * wm + 16 * mt + g + 8 * half_;
                const float thr = __int_as_float(s_min[r]) + M_COLLECT;
                if (rmin_c[mt][half_] <= thr) {   // rare: this group holds a candidate
                    #pragma unroll
                    for (int nt = 0; nt < 4; nt++) {
                        const int c = ct * 64 + 32 * wn + 8 * nt + 2 * tg;
                        #pragma unroll
                        for (int e = 0; e < 2; e++) {
                            float en = e ? enp[nt].y : enp[nt].x;
                            float dv = en - 2.0f * acc[mt][nt][2 * half_ + e];
                            if (dv <= thr) {
                                int p = atomicAdd(&s_cnt[r], 1);
                                if (p < CAP) {
                                    size_t gi = (size_t)(r0 + r) * CAP + p;
                                    g_cand_d[gi] = dv;
                                    g_cand_i[gi] = c + e;
                                }
                            }
                        }
                    }
                }
            }
        }
        // zero accumulators for the next tile
        #pragma unroll
        for (int mt = 0; mt < 2; mt++)
            #pragma unroll
            for (int nt = 0; nt < 4; nt++)
                #pragma unroll
                for (int e = 0; e < 4; e++) acc[mt][nt][e] = 0.0f;

        CP_WAIT0();
        __syncthreads();
    }

    if (tid < 128) {
        g_rowmin[r0 + tid] = __int_as_float(s_min[tid]);
        g_ccnt[r0 + tid]   = s_cnt[tid];
    }
}

// --------------------------------------------------------------------------
// Pass 2: one warp per row — filter (offset space), rare exact fp32 rescore
// (true-distance space, zn inline), gather, output, loss partial; last block
// finalizes the loss scalar.
// --------------------------------------------------------------------------
__device__ __forceinline__ float warp_sum(float v) {
    #pragma unroll
    for (int off = 16; off > 0; off >>= 1) v += __shfl_xor_sync(0xffffffffu, v, off);
    return v;
}

__global__ __launch_bounds__(512)
void pass2_kernel(const float* __restrict__ z, const float* __restrict__ emb,
                  float* __restrict__ out) {
    __shared__ float s_l[16];
    __shared__ double sd[512];
    __shared__ bool amLast;
    const int tid  = threadIdx.x;
    const int lane = tid & 31;
    const int row  = blockIdx.x * 16 + (tid >> 5);
    const float* zr = z + (size_t)row * DIM;
    const float4 z1 = *(const float4*)(zr + lane * 8);
    const float4 z2 = *(const float4*)(zr + lane * 8 + 4);
    const float zn = warp_sum(z1.x*z1.x + z1.y*z1.y + z1.z*z1.z + z1.w*z1.w
                            + z2.x*z2.x + z2.y*z2.y + z2.z*z2.z + z2.w*z2.w);

    int widx;
    const int cnt = g_ccnt[row];
    if (cnt > CAP) {
        float bd = 3.4e38f; int bi = 0;
        for (int c = 0; c < KCODES; c++) {
            const float* er = emb + (size_t)c * DIM;
            float4 e1 = *(const float4*)(er + lane * 8);
            float4 e2 = *(const float4*)(er + lane * 8 + 4);
            float dot = z1.x*e1.x + z1.y*e1.y + z1.z*e1.z + z1.w*e1.w
                      + z2.x*e2.x + z2.y*e2.y + z2.z*e2.z + z2.w*e2.w;
            dot = warp_sum(dot);
            float d = (zn + g_enorm[c]) - 2.0f * dot;
            if (d < bd) { bd = d; bi = c; }
        }
        widx = bi;
    } else {
        const float vmin = g_rowmin[row];
        float cd = 3.4e38f; int ci = -1;
        if (lane < cnt) {
            cd = g_cand_d[(size_t)row * CAP + lane];
            ci = g_cand_i[(size_t)row * CAP + lane];
        }
        unsigned keep = __ballot_sync(0xffffffffu, cd <= vmin + M_KEEP);
        if (__popc(keep) == 1) {
            widx = __shfl_sync(0xffffffffu, ci, __ffs(keep) - 1);
        } else {
            float bd = 3.4e38f; int bi = 0x7fffffff;
            unsigned m = keep;
            while (m) {
                int src = __ffs(m) - 1; m &= m - 1;
                int c = __shfl_sync(0xffffffffu, ci, src);
                const float* er = emb + (size_t)c * DIM;
                float4 e1 = *(const float4*)(er + lane * 8);
                float4 e2 = *(const float4*)(er + lane * 8 + 4);
                float dot = z1.x*e1.x + z1.y*e1.y + z1.z*e1.z + z1.w*e1.w
                          + z2.x*e2.x + z2.y*e2.y + z2.z*e2.z + z2.w*e2.w;
                dot = warp_sum(dot);
                float d = (zn + g_enorm[c]) - 2.0f * dot;
                if (d < bd || (d == bd && c < bi)) { bd = d; bi = c; }
            }
            widx = bi;
        }
    }

    const float* er = emb + (size_t)widx * DIM;
    float4 e1 = *(const float4*)(er + lane * 8);
    float4 e2 = *(const float4*)(er + lane * 8 + 4);
    float d0 = e1.x - z1.x, d1 = e1.y - z1.y, d2 = e1.z - z1.z, d3 = e1.w - z1.w;
    float d4 = e2.x - z2.x, d5 = e2.y - z2.y, d6 = e2.z - z2.z, d7 = e2.w - z2.w;
    float4 o1 = make_float4(z1.x + d0, z1.y + d1, z1.z + d2, z1.w + d3);
    float4 o2 = make_float4(z2.x + d4, z2.y + d5, z2.z + d6, z2.w + d7);
    *(float4*)(out + (size_t)row * DIM + lane * 8)     = o1;
    *(float4*)(out + (size_t)row * DIM + lane * 8 + 4) = o2;
    float lsum = d0*d0 + d1*d1 + d2*d2 + d3*d3 + d4*d4 + d5*d5 + d6*d6 + d7*d7;
    lsum = warp_sum(lsum);
    if (lane == 0) s_l[tid >> 5] = lsum;
    __syncthreads();
    if (tid == 0) {
        double acc = 0.0;
        #pragma unroll
        for (int i = 0; i < 16; i++) acc += (double)s_l[i];
        g_partial[blockIdx.x] = acc;
        __threadfence();
        amLast = (atomicAdd(&g_done, 1) == NP2 - 1);
    }
    __syncthreads();

    if (amLast) {
        double a = 0.0;
        #pragma unroll
        for (int i = 0; i < NP2 / 512; i++) a += g_partial[tid + i * 512];
        sd[tid] = a;
        __syncthreads();
        for (int st = 256; st > 0; st >>= 1) {
            if (tid < st) sd[tid] += sd[tid + st];
            __syncthreads();
        }
        if (tid == 0) {
            float m = (float)(sd[0] / ((double)N_ROWS * (double)DIM));
            out[(size_t)N_ROWS * DIM] = m + 0.25f * m;
        }
    }
}

extern "C" void kernel_launch(void* const* d_in, const int* in_sizes, int n_in,
                              void* d_out, int out_size) {
    const float* z   = (const float*)d_in[0];
    const float* emb = (const float*)d_in[1];
    float* out = (float*)d_out;

    static int cfg_done = 0;
    if (!cfg_done) {
        cudaFuncSetAttribute(pass1_kernel, cudaFuncAttributeMaxDynamicSharedMemorySize, SMEM1);
        cfg_done = 1;
    }

    prep_kernel<<<KCODES / 8, 256>>>(emb);
    pass1_kernel<<<N_ROWS / 128, 256, SMEM1>>>(z);
    pass2_kernel<<<NP2, 512>>>(z, emb, out);
}